// round 3
// baseline (speedup 1.0000x reference)
#include <cuda_runtime.h>

// Problem constants
#define NB    8
#define LPC   2500
#define C_    14
#define K_    9
#define N_    (NB*LPC)     // 20000
#define E_    (N_*K_)      // 180000
#define HID_  128
#define NCLS_ 20
#define XDIM  (C_*3)       // 42

// Scratch (static device globals; no allocation allowed)
__device__ float g_X[2][N_*XDIM];
__device__ float g_h[N_*HID_];
__device__ float g_aggm[N_*HID_];
__device__ int   g_dst[E_];
__device__ float g_classh[NCLS_*HID_];
__device__ float g_classcw[NCLS_*C_];

__device__ __forceinline__ float silu_f(float x) {
    return x * (1.0f / (1.0f + __expf(-x)));
}

// ---------------------------------------------------------------------------
// kNN on CA coords (channel 1). One thread per query node, tiled candidates.
// ---------------------------------------------------------------------------
__global__ void __launch_bounds__(256) knn_kernel(const float* __restrict__ X) {
    int b = blockIdx.y;
    int q = blockIdx.x * 256 + threadIdx.x;
    __shared__ float sx[256], sy[256], sz[256];

    float qx = 0.f, qy = 0.f, qz = 0.f;
    if (q < LPC) {
        const float* p = X + ((size_t)(b*LPC + q) * C_ + 1) * 3;
        qx = p[0]; qy = p[1]; qz = p[2];
    }
    float best[K_]; int bidx[K_];
    #pragma unroll
    for (int k = 0; k < K_; k++) { best[k] = 3.0e38f; bidx[k] = 0; }

    for (int base = 0; base < LPC; base += 256) {
        int c = base + threadIdx.x;
        if (c < LPC) {
            const float* p = X + ((size_t)(b*LPC + c) * C_ + 1) * 3;
            sx[threadIdx.x] = p[0]; sy[threadIdx.x] = p[1]; sz[threadIdx.x] = p[2];
        }
        __syncthreads();
        int tl = min(256, LPC - base);
        if (q < LPC) {
            for (int j = 0; j < tl; j++) {
                int cj = base + j;
                if (cj == q) continue;
                float dx = qx - sx[j], dy = qy - sy[j], dz = qz - sz[j];
                float d2 = dx*dx + dy*dy + dz*dz;
                if (d2 < best[K_-1]) {
                    int pos = K_-1;
                    while (pos > 0 && best[pos-1] > d2) {
                        best[pos] = best[pos-1]; bidx[pos] = bidx[pos-1]; pos--;
                    }
                    best[pos] = d2; bidx[pos] = cj;
                }
            }
        }
        __syncthreads();
    }
    if (q < LPC) {
        int n = b*LPC + q;
        #pragma unroll
        for (int k = 0; k < K_; k++) g_dst[n*K_ + k] = b*LPC + bidx[k];
    }
}

// ---------------------------------------------------------------------------
// Per-class precompute: class_h = E_tab @ Win, class_cw = softmax(Wchan)
// ---------------------------------------------------------------------------
__global__ void __launch_bounds__(128) class_kernel(
    const float* __restrict__ E_tab, const float* __restrict__ Win,
    const float* __restrict__ Wchan)
{
    int c = blockIdx.x;
    int j = threadIdx.x;
    __shared__ float emb[HID_];
    emb[j] = E_tab[c*HID_ + j];
    __syncthreads();
    float acc = 0.f;
    #pragma unroll 4
    for (int k = 0; k < HID_; k++) acc += emb[k] * Win[k*HID_ + j];
    g_classh[c*HID_ + j] = acc;
    if (j == 0) {
        float w[C_]; float mx = -1e30f;
        #pragma unroll
        for (int a = 0; a < C_; a++) { w[a] = Wchan[c*C_ + a]; mx = fmaxf(mx, w[a]); }
        float s = 0.f;
        #pragma unroll
        for (int a = 0; a < C_; a++) { w[a] = expf(w[a] - mx); s += w[a]; }
        float inv = 1.0f / s;
        #pragma unroll
        for (int a = 0; a < C_; a++) g_classcw[c*C_ + a] = w[a] * inv;
    }
}

__global__ void __launch_bounds__(256) gather_h_kernel(const int* __restrict__ S) {
    int idx = blockIdx.x * 256 + threadIdx.x;
    if (idx < N_ * HID_) {
        int i = idx >> 7, j = idx & 127;
        g_h[idx] = g_classh[S[i]*HID_ + j];
    }
}

// ---------------------------------------------------------------------------
// Edge + per-node aggregation kernel: one block per source node (9 edges).
// Weights indexed per-layer via pre-offset pointers.
// ---------------------------------------------------------------------------
__global__ void __launch_bounds__(128) edge_kernel(
    int layer, const float* __restrict__ Xext,
    const int* __restrict__ S,
    const float* __restrict__ Wr,  const float* __restrict__ We1,
    const float* __restrict__ be1, const float* __restrict__ We2,
    const float* __restrict__ Wx1, const float* __restrict__ Wx2)
{
    const float* Xin  = (layer == 0) ? Xext : g_X[(layer + 1) & 1];
    float*       Xout = g_X[layer & 1];

    int i   = blockIdx.x;
    int tid = threadIdx.x;

    __shared__ float s_xd[K_][XDIM];
    __shared__ float s_hsrc[HID_];
    __shared__ float s_hdst[K_][HID_];
    __shared__ float s_rad[K_][C_*C_];
    __shared__ float s_rf[K_][HID_];
    __shared__ float s_m1[K_][HID_];
    __shared__ float s_m[K_][HID_];
    __shared__ float s_t[K_][HID_];
    __shared__ float s_cw[K_][C_];
    __shared__ int   s_dst[K_];

    if (tid < K_) s_dst[tid] = g_dst[i*K_ + tid];
    s_hsrc[tid] = g_h[i*HID_ + tid];
    __syncthreads();

    // h_dst gather (coalesced per edge row)
    #pragma unroll
    for (int e = 0; e < K_; e++)
        s_hdst[e][tid] = g_h[s_dst[e]*HID_ + tid];

    // xd = X[src] - X[dst]
    const float* Xi = Xin + (size_t)i * XDIM;
    for (int idx = tid; idx < K_*XDIM; idx += 128) {
        int e = idx / XDIM, r = idx % XDIM;
        s_xd[e][r] = Xi[r] - Xin[(size_t)s_dst[e]*XDIM + r];
    }
    __syncthreads();

    // rad[e][c*C+d] = dot3(xd[c], xd[d]) / C
    for (int idx = tid; idx < K_*C_*C_; idx += 128) {
        int e = idx / (C_*C_), p = idx % (C_*C_);
        int c = p / C_, d = p % C_;
        const float* a = &s_xd[e][c*3];
        const float* b = &s_xd[e][d*3];
        s_rad[e][p] = (a[0]*b[0] + a[1]*b[1] + a[2]*b[2]) * (1.0f / C_);
    }
    __syncthreads();

    // rfeat = rad @ Wr  (thread tid owns output col tid, 9 accumulators)
    {
        float acc[K_];
        #pragma unroll
        for (int e = 0; e < K_; e++) acc[e] = 0.f;
        #pragma unroll 4
        for (int k = 0; k < C_*C_; k++) {
            float w = Wr[k*HID_ + tid];
            #pragma unroll
            for (int e = 0; e < K_; e++) acc[e] += s_rad[e][k] * w;
        }
        #pragma unroll
        for (int e = 0; e < K_; e++) s_rf[e][tid] = acc[e];
    }

    // source contribution of We1 (identical across the node's 9 edges)
    float basej = be1[tid];
    #pragma unroll 4
    for (int k = 0; k < HID_; k++) basej += s_hsrc[k] * We1[k*HID_ + tid];
    __syncthreads();

    // m1 = silu(concat(h_src, h_dst, rfeat) @ We1 + be1)
    {
        float acc[K_];
        #pragma unroll
        for (int e = 0; e < K_; e++) acc[e] = basej;
        #pragma unroll 4
        for (int k = 0; k < HID_; k++) {
            float w = We1[(HID_ + k)*HID_ + tid];
            #pragma unroll
            for (int e = 0; e < K_; e++) acc[e] += s_hdst[e][k] * w;
        }
        #pragma unroll 4
        for (int k = 0; k < HID_; k++) {
            float w = We1[(2*HID_ + k)*HID_ + tid];
            #pragma unroll
            for (int e = 0; e < K_; e++) acc[e] += s_rf[e][k] * w;
        }
        #pragma unroll
        for (int e = 0; e < K_; e++) s_m1[e][tid] = silu_f(acc[e]);
    }
    __syncthreads();

    // m = silu(m1 @ We2)
    {
        float acc[K_];
        #pragma unroll
        for (int e = 0; e < K_; e++) acc[e] = 0.f;
        #pragma unroll 4
        for (int k = 0; k < HID_; k++) {
            float w = We2[k*HID_ + tid];
            #pragma unroll
            for (int e = 0; e < K_; e++) acc[e] += s_m1[e][k] * w;
        }
        #pragma unroll
        for (int e = 0; e < K_; e++) s_m[e][tid] = silu_f(acc[e]);
    }
    __syncthreads();

    // t = silu(m @ Wx1)
    {
        float acc[K_];
        #pragma unroll
        for (int e = 0; e < K_; e++) acc[e] = 0.f;
        #pragma unroll 4
        for (int k = 0; k < HID_; k++) {
            float w = Wx1[k*HID_ + tid];
            #pragma unroll
            for (int e = 0; e < K_; e++) acc[e] += s_m[e][k] * w;
        }
        #pragma unroll
        for (int e = 0; e < K_; e++) s_t[e][tid] = silu_f(acc[e]);
    }
    __syncthreads();

    // coef = (t @ Wx2) * cw_src
    if (tid < K_*C_) {
        int e = tid / C_, c = tid % C_;
        float acc = 0.f;
        #pragma unroll 4
        for (int k = 0; k < HID_; k++) acc += s_t[e][k] * Wx2[k*C_ + c];
        s_cw[e][c] = acc * g_classcw[S[i]*C_ + c];
    }
    __syncthreads();

    // X update: Xout[i] = X[i] + sum_e xd*coefw / K  (no atomics: edges grouped by src)
    if (tid < XDIM) {
        int c = tid / 3;
        float sacc = 0.f;
        #pragma unroll
        for (int e = 0; e < K_; e++) sacc += s_xd[e][tid] * s_cw[e][c];
        Xout[(size_t)i*XDIM + tid] = Xi[tid] + sacc * (1.0f / K_);
    }

    // aggm[i] = sum_e m[e]
    {
        float am = 0.f;
        #pragma unroll
        for (int e = 0; e < K_; e++) am += s_m[e][tid];
        g_aggm[i*HID_ + tid] = am;
    }
}

// ---------------------------------------------------------------------------
// Node update: h += silu(concat(h, aggm) @ Wh1) @ Wh2
// ---------------------------------------------------------------------------
__global__ void __launch_bounds__(128) node_kernel(
    const float* __restrict__ Wh1, const float* __restrict__ Wh2)
{
    int i = blockIdx.x, j = threadIdx.x;
    __shared__ float hl[HID_], am[HID_], u[HID_];
    hl[j] = g_h[i*HID_ + j];
    am[j] = g_aggm[i*HID_ + j];
    __syncthreads();
    float acc = 0.f;
    #pragma unroll 4
    for (int k = 0; k < HID_; k++) acc += hl[k] * Wh1[k*HID_ + j];
    #pragma unroll 4
    for (int k = 0; k < HID_; k++) acc += am[k] * Wh1[(HID_ + k)*HID_ + j];
    u[j] = silu_f(acc);
    __syncthreads();
    float acc2 = 0.f;
    #pragma unroll 4
    for (int k = 0; k < HID_; k++) acc2 += u[k] * Wh2[k*HID_ + j];
    g_h[i*HID_ + j] = hl[j] + acc2;
}

// ---------------------------------------------------------------------------
// Final: logits = silu(silu(h) @ Wf1) @ Wf2 ; also emit final X.
// Output layout: [logits (N*20)] then [X (N*42)], fp32.
// ---------------------------------------------------------------------------
__global__ void __launch_bounds__(128) final_kernel(
    const float* __restrict__ Wf1, const float* __restrict__ Wf2,
    float* __restrict__ out)
{
    int i = blockIdx.x, j = threadIdx.x;
    __shared__ float s1[HID_], u[HID_];
    s1[j] = silu_f(g_h[i*HID_ + j]);
    __syncthreads();
    float acc = 0.f;
    #pragma unroll 4
    for (int k = 0; k < HID_; k++) acc += s1[k] * Wf1[k*HID_ + j];
    u[j] = silu_f(acc);
    __syncthreads();
    if (j < NCLS_) {
        float acc2 = 0.f;
        #pragma unroll 4
        for (int k = 0; k < HID_; k++) acc2 += u[k] * Wf2[k*NCLS_ + j];
        out[(size_t)i*NCLS_ + j] = acc2;
    }
    // final X lives in g_X[0] after 3 layers (0->buf0, 1->buf1, 2->buf0)
    const float* Xf = g_X[0];
    for (int idx = j; idx < XDIM; idx += 128)
        out[(size_t)N_*NCLS_ + (size_t)i*XDIM + idx] = Xf[(size_t)i*XDIM + idx];
}

// ---------------------------------------------------------------------------
extern "C" void kernel_launch(void* const* d_in, const int* in_sizes, int n_in,
                              void* d_out, int out_size)
{
    const float* X     = (const float*)d_in[0];
    const int*   S     = (const int*)  d_in[1];
    const float* E_tab = (const float*)d_in[2];
    const float* Wchan = (const float*)d_in[3];
    const float* Win   = (const float*)d_in[4];
    const float* Wr    = (const float*)d_in[5];
    const float* We1   = (const float*)d_in[6];
    const float* be1   = (const float*)d_in[7];
    const float* We2   = (const float*)d_in[8];
    const float* Wx1   = (const float*)d_in[9];
    const float* Wx2   = (const float*)d_in[10];
    const float* Wh1   = (const float*)d_in[11];
    const float* Wh2   = (const float*)d_in[12];
    const float* Wf1   = (const float*)d_in[13];
    const float* Wf2   = (const float*)d_in[14];
    float* out = (float*)d_out;

    dim3 kg((LPC + 255) / 256, NB);
    knn_kernel<<<kg, 256>>>(X);
    class_kernel<<<NCLS_, HID_>>>(E_tab, Win, Wchan);
    gather_h_kernel<<<(N_*HID_ + 255) / 256, 256>>>(S);

    for (int l = 0; l < 3; l++) {
        edge_kernel<<<N_, 128>>>(l, X, S,
            Wr  + (size_t)l * C_*C_*HID_,
            We1 + (size_t)l * 3*HID_*HID_,
            be1 + (size_t)l * HID_,
            We2 + (size_t)l * HID_*HID_,
            Wx1 + (size_t)l * HID_*HID_,
            Wx2 + (size_t)l * HID_*C_);
        node_kernel<<<N_, 128>>>(
            Wh1 + (size_t)l * 2*HID_*HID_,
            Wh2 + (size_t)l * HID_*HID_);
    }

    final_kernel<<<N_, 128>>>(Wf1, Wf2, out);
}

// round 4
// speedup vs baseline: 1.0715x; 1.0715x over previous
#include <cuda_runtime.h>

// Problem constants
#define NB    8
#define LPC   2500
#define C_    14
#define K_    9
#define N_    (NB*LPC)     // 20000
#define E_    (N_*K_)      // 180000
#define HID_  128
#define NCLS_ 20
#define XDIM  (C_*3)       // 42

#define NPB   2            // nodes per edge-block
#define ROWS  (NPB*K_)     // 18 edges per block
#define NNB   16           // nodes per node/final block

typedef unsigned long long ull;

// Scratch (static device globals; no allocation allowed)
__device__ __align__(16) float g_X[2][N_*XDIM];
__device__ __align__(16) float g_h[N_*HID_];
__device__ __align__(16) float g_aggm[N_*HID_];
__device__ int   g_dst[E_];
__device__ __align__(16) float g_classh[NCLS_*HID_];
__device__ float g_classcw[NCLS_*C_];

// Packed weights: layout [k/4][128 cols][4 k] -> coalesced LDG.128, 4 k/thread
__device__ __align__(16) float g_WrP [3][49*128*4];   // k=196
__device__ __align__(16) float g_We1P[3][96*128*4];   // k=384
__device__ __align__(16) float g_We2P[3][32*128*4];   // k=128
__device__ __align__(16) float g_Wx1P[3][32*128*4];   // k=128
__device__ __align__(16) float g_Wh1P[3][64*128*4];   // k=256
__device__ __align__(16) float g_Wh2P[3][32*128*4];   // k=128
__device__ __align__(16) float g_Wf1P[32*128*4];      // k=128
// Small matrices: plain transpose [out_col][k]
__device__ __align__(16) float g_Wx2T[3][C_][HID_];
__device__ __align__(16) float g_Wf2T[NCLS_][HID_];

__device__ __forceinline__ float silu_f(float x) {
    return x * (1.0f / (1.0f + __expf(-x)));
}

// packed f32x2 FMA: acc.{lo,hi} += a.{lo,hi} * w.{lo,hi}
__device__ __forceinline__ void fma2(ull& acc, ull a, ull w) {
    asm("fma.rn.f32x2 %0, %1, %2, %0;" : "+l"(acc) : "l"(a), "l"(w));
}
__device__ __forceinline__ float hadd2(ull v) {
    unsigned lo, hi;
    asm("mov.b64 {%0,%1}, %2;" : "=r"(lo), "=r"(hi) : "l"(v));
    return __uint_as_float(lo) + __uint_as_float(hi);
}
__device__ __forceinline__ ulonglong2 ld2u(const float* p) {
    return *reinterpret_cast<const ulonglong2*>(p);
}

// ---------------------------------------------------------------------------
// Weight repack: in[k][128] -> out[k/4][128][4]
// ---------------------------------------------------------------------------
__global__ void __launch_bounds__(256) pack_kernel(
    const float* __restrict__ in, int which, int l, int Kk)
{
    int idx = blockIdx.x * 256 + threadIdx.x;
    if (idx >= Kk * 128) return;
    int k = idx >> 7, c = idx & 127;
    float v = in[k*128 + c];
    float* out;
    switch (which) {
        case 0: out = g_WrP[l];  break;
        case 1: out = g_We1P[l]; break;
        case 2: out = g_We2P[l]; break;
        case 3: out = g_Wx1P[l]; break;
        case 4: out = g_Wh1P[l]; break;
        case 5: out = g_Wh2P[l]; break;
        default: out = g_Wf1P;   break;
    }
    out[(k >> 2)*512 + (c << 2) + (k & 3)] = v;
}

// Plain transpose: in[R][Cc] -> out[Cc][R]
__global__ void __launch_bounds__(256) tr_kernel(
    const float* __restrict__ in, int which, int l, int R, int Cc)
{
    int idx = blockIdx.x * 256 + threadIdx.x;
    if (idx >= R * Cc) return;
    int r = idx / Cc, c = idx - r*Cc;
    float* out = (which == 0) ? &g_Wx2T[l][0][0] : &g_Wf2T[0][0];
    out[c*R + r] = in[r*Cc + c];
}

// ---------------------------------------------------------------------------
// kNN on CA coords (channel 1). One thread per query node, tiled candidates.
// ---------------------------------------------------------------------------
__global__ void __launch_bounds__(256) knn_kernel(const float* __restrict__ X) {
    int b = blockIdx.y;
    int q = blockIdx.x * 256 + threadIdx.x;
    __shared__ float sx[256], sy[256], sz[256];

    float qx = 0.f, qy = 0.f, qz = 0.f;
    if (q < LPC) {
        const float* p = X + ((size_t)(b*LPC + q) * C_ + 1) * 3;
        qx = p[0]; qy = p[1]; qz = p[2];
    }
    float best[K_]; int bidx[K_];
    #pragma unroll
    for (int k = 0; k < K_; k++) { best[k] = 3.0e38f; bidx[k] = 0; }

    for (int base = 0; base < LPC; base += 256) {
        int c = base + threadIdx.x;
        if (c < LPC) {
            const float* p = X + ((size_t)(b*LPC + c) * C_ + 1) * 3;
            sx[threadIdx.x] = p[0]; sy[threadIdx.x] = p[1]; sz[threadIdx.x] = p[2];
        }
        __syncthreads();
        int tl = min(256, LPC - base);
        if (q < LPC) {
            for (int j = 0; j < tl; j++) {
                int cj = base + j;
                if (cj == q) continue;
                float dx = qx - sx[j], dy = qy - sy[j], dz = qz - sz[j];
                float d2 = dx*dx + dy*dy + dz*dz;
                if (d2 < best[K_-1]) {
                    int pos = K_-1;
                    while (pos > 0 && best[pos-1] > d2) {
                        best[pos] = best[pos-1]; bidx[pos] = bidx[pos-1]; pos--;
                    }
                    best[pos] = d2; bidx[pos] = cj;
                }
            }
        }
        __syncthreads();
    }
    if (q < LPC) {
        int n = b*LPC + q;
        #pragma unroll
        for (int k = 0; k < K_; k++) g_dst[n*K_ + k] = b*LPC + bidx[k];
    }
}

// ---------------------------------------------------------------------------
// Per-class precompute: class_h = E_tab @ Win, class_cw = softmax(Wchan)
// ---------------------------------------------------------------------------
__global__ void __launch_bounds__(128) class_kernel(
    const float* __restrict__ E_tab, const float* __restrict__ Win,
    const float* __restrict__ Wchan)
{
    int c = blockIdx.x;
    int j = threadIdx.x;
    __shared__ float emb[HID_];
    emb[j] = E_tab[c*HID_ + j];
    __syncthreads();
    float acc = 0.f;
    #pragma unroll 4
    for (int k = 0; k < HID_; k++) acc += emb[k] * Win[k*HID_ + j];
    g_classh[c*HID_ + j] = acc;
    if (j == 0) {
        float w[C_]; float mx = -1e30f;
        #pragma unroll
        for (int a = 0; a < C_; a++) { w[a] = Wchan[c*C_ + a]; mx = fmaxf(mx, w[a]); }
        float s = 0.f;
        #pragma unroll
        for (int a = 0; a < C_; a++) { w[a] = expf(w[a] - mx); s += w[a]; }
        float inv = 1.0f / s;
        #pragma unroll
        for (int a = 0; a < C_; a++) g_classcw[c*C_ + a] = w[a] * inv;
    }
}

__global__ void __launch_bounds__(256) gather_h_kernel(const int* __restrict__ S) {
    int idx = blockIdx.x * 256 + threadIdx.x;
    if (idx < N_ * HID_) {
        int i = idx >> 7, j = idx & 127;
        g_h[idx] = g_classh[S[i]*HID_ + j];
    }
}

// ---------------------------------------------------------------------------
// Edge kernel: 2 source nodes (18 edges) per block. f32x2 inner loops,
// packed weights, shared-buffer aliasing.
// ---------------------------------------------------------------------------
__global__ void __launch_bounds__(128) edge_kernel(
    int layer, const float* __restrict__ Xext, const int* __restrict__ S,
    const float* __restrict__ be1)
{
    const float* Xin  = (layer == 0) ? Xext : g_X[(layer + 1) & 1];
    float*       Xout = g_X[layer & 1];
    const float* WrP  = g_WrP[layer];
    const float* We1P = g_We1P[layer];
    const float* We2P = g_We2P[layer];
    const float* Wx1P = g_Wx1P[layer];
    const float* Wx2T = &g_Wx2T[layer][0][0];

    const int tid = threadIdx.x;
    const int i0  = blockIdx.x * NPB;

    __shared__ __align__(16) float s_xd[ROWS][XDIM];
    __shared__ __align__(16) float s_hsrc[NPB][HID_];
    __shared__ __align__(16) float s_bufA[ROWS][HID_];   // hdst -> m
    __shared__ __align__(16) float s_bufB[ROWS][196];    // rad  -> m1 (first 128)
    __shared__ __align__(16) float s_bufC[ROWS][HID_];   // rf   -> t
    __shared__ float s_cw[ROWS][16];
    __shared__ int   s_dst[ROWS];

    if (tid < ROWS) s_dst[tid] = g_dst[i0*K_ + tid];
    #pragma unroll
    for (int p = 0; p < NPB; p++)
        s_hsrc[p][tid] = g_h[(i0+p)*HID_ + tid];
    __syncthreads();

    // h_dst gather (coalesced row loads)
    #pragma unroll
    for (int r = 0; r < ROWS; r++)
        s_bufA[r][tid] = g_h[(size_t)s_dst[r]*HID_ + tid];

    // xd = X[src] - X[dst]
    for (int idx = tid; idx < ROWS*XDIM; idx += 128) {
        int r = idx / XDIM, q = idx - r*XDIM;
        int p = r / K_;
        s_xd[r][q] = Xin[(size_t)(i0+p)*XDIM + q] - Xin[(size_t)s_dst[r]*XDIM + q];
    }
    __syncthreads();

    // rad[r][c*C+d] = dot3(xd[c], xd[d]) / C
    #pragma unroll 1
    for (int r = 0; r < ROWS; r++) {
        for (int p = tid; p < C_*C_; p += 128) {
            int c = p / C_, d = p - c*C_;
            const float* a = &s_xd[r][c*3];
            const float* b = &s_xd[r][d*3];
            s_bufB[r][p] = (a[0]*b[0] + a[1]*b[1] + a[2]*b[2]) * (1.0f/C_);
        }
    }
    __syncthreads();

    // rf = rad @ Wr -> bufC
    {
        ull acc[ROWS];
        #pragma unroll
        for (int r = 0; r < ROWS; r++) acc[r] = 0ULL;
        const float* wp = WrP + (tid << 2);
        #pragma unroll 1
        for (int k4 = 0; k4 < 49; k4++) {
            ulonglong2 w = ld2u(wp + k4*512);
            #pragma unroll
            for (int r = 0; r < ROWS; r++) {
                ulonglong2 a = ld2u(&s_bufB[r][k4 << 2]);
                fma2(acc[r], a.x, w.x);
                fma2(acc[r], a.y, w.y);
            }
        }
        #pragma unroll
        for (int r = 0; r < ROWS; r++) s_bufC[r][tid] = hadd2(acc[r]);
    }

    // per-node source base of We1 (first 128 k of We1)
    float base0, base1;
    {
        ull b[NPB];
        #pragma unroll
        for (int p = 0; p < NPB; p++) b[p] = 0ULL;
        const float* wp = We1P + (tid << 2);
        #pragma unroll 1
        for (int k4 = 0; k4 < 32; k4++) {
            ulonglong2 w = ld2u(wp + k4*512);
            #pragma unroll
            for (int p = 0; p < NPB; p++) {
                ulonglong2 a = ld2u(&s_hsrc[p][k4 << 2]);
                fma2(b[p], a.x, w.x);
                fma2(b[p], a.y, w.y);
            }
        }
        float bb = be1[tid];
        base0 = bb + hadd2(b[0]);
        base1 = bb + hadd2(b[1]);
    }
    __syncthreads();   // rf complete; rad fully consumed

    // m1 = silu(base + hdst@We1[128:256] + rf@We1[256:384]) -> bufB (stride 196)
    {
        ull acc[ROWS];
        #pragma unroll
        for (int r = 0; r < ROWS; r++) acc[r] = 0ULL;
        const float* wp = We1P + 32*512 + (tid << 2);
        #pragma unroll 1
        for (int k4 = 0; k4 < 32; k4++) {
            ulonglong2 w = ld2u(wp + k4*512);
            #pragma unroll
            for (int r = 0; r < ROWS; r++) {
                ulonglong2 a = ld2u(&s_bufA[r][k4 << 2]);
                fma2(acc[r], a.x, w.x);
                fma2(acc[r], a.y, w.y);
            }
        }
        const float* wp2 = We1P + 64*512 + (tid << 2);
        #pragma unroll 1
        for (int k4 = 0; k4 < 32; k4++) {
            ulonglong2 w = ld2u(wp2 + k4*512);
            #pragma unroll
            for (int r = 0; r < ROWS; r++) {
                ulonglong2 a = ld2u(&s_bufC[r][k4 << 2]);
                fma2(acc[r], a.x, w.x);
                fma2(acc[r], a.y, w.y);
            }
        }
        #pragma unroll
        for (int r = 0; r < ROWS; r++) {
            float v = ((r < K_) ? base0 : base1) + hadd2(acc[r]);
            s_bufB[r][tid] = silu_f(v);
        }
    }
    __syncthreads();

    // m = silu(m1 @ We2) -> bufA
    {
        ull acc[ROWS];
        #pragma unroll
        for (int r = 0; r < ROWS; r++) acc[r] = 0ULL;
        const float* wp = We2P + (tid << 2);
        #pragma unroll 1
        for (int k4 = 0; k4 < 32; k4++) {
            ulonglong2 w = ld2u(wp + k4*512);
            #pragma unroll
            for (int r = 0; r < ROWS; r++) {
                ulonglong2 a = ld2u(&s_bufB[r][k4 << 2]);
                fma2(acc[r], a.x, w.x);
                fma2(acc[r], a.y, w.y);
            }
        }
        #pragma unroll
        for (int r = 0; r < ROWS; r++) s_bufA[r][tid] = silu_f(hadd2(acc[r]));
    }
    __syncthreads();

    // t = silu(m @ Wx1) -> bufC
    {
        ull acc[ROWS];
        #pragma unroll
        for (int r = 0; r < ROWS; r++) acc[r] = 0ULL;
        const float* wp = Wx1P + (tid << 2);
        #pragma unroll 1
        for (int k4 = 0; k4 < 32; k4++) {
            ulonglong2 w = ld2u(wp + k4*512);
            #pragma unroll
            for (int r = 0; r < ROWS; r++) {
                ulonglong2 a = ld2u(&s_bufA[r][k4 << 2]);
                fma2(acc[r], a.x, w.x);
                fma2(acc[r], a.y, w.y);
            }
        }
        #pragma unroll
        for (int r = 0; r < ROWS; r++) s_bufC[r][tid] = silu_f(hadd2(acc[r]));
    }
    __syncthreads();

    // coef[r][c] = (t[r] . Wx2T[c]) * classcw ; 252 outputs
    for (int q = tid; q < ROWS*C_; q += 128) {
        int r = q / C_, c = q - r*C_;
        ull a2 = 0ULL;
        const float* wrow = Wx2T + c*HID_;
        #pragma unroll 1
        for (int k4 = 0; k4 < 32; k4++) {
            ulonglong2 w = ld2u(wrow + (k4 << 2));
            ulonglong2 a = ld2u(&s_bufC[r][k4 << 2]);
            fma2(a2, a.x, w.x);
            fma2(a2, a.y, w.y);
        }
        int p = r / K_;
        s_cw[r][c] = hadd2(a2) * g_classcw[S[i0+p]*C_ + c];
    }

    // aggm (reads bufA = m)
    #pragma unroll
    for (int p = 0; p < NPB; p++) {
        float am = 0.f;
        #pragma unroll
        for (int e = 0; e < K_; e++) am += s_bufA[p*K_ + e][tid];
        g_aggm[(i0+p)*HID_ + tid] = am;
    }
    __syncthreads();

    // X update (no atomics: all edges of node i live in this block)
    if (tid < NPB*XDIM) {
        int p = tid / XDIM, q = tid - p*XDIM, c = q / 3;
        float s = 0.f;
        #pragma unroll
        for (int e = 0; e < K_; e++) s += s_xd[p*K_ + e][q] * s_cw[p*K_ + e][c];
        Xout[(size_t)(i0+p)*XDIM + q] = Xin[(size_t)(i0+p)*XDIM + q] + s * (1.0f/K_);
    }
}

// ---------------------------------------------------------------------------
// Node update, 16 nodes per block: h += silu([h|aggm] @ Wh1) @ Wh2
// ---------------------------------------------------------------------------
__global__ void __launch_bounds__(128) node_kernel(int layer) {
    const float* W1P = g_Wh1P[layer];
    const float* W2P = g_Wh2P[layer];
    int i0  = blockIdx.x * NNB;
    int tid = threadIdx.x;
    __shared__ __align__(16) float s_h[NNB][HID_];
    __shared__ __align__(16) float s_am[NNB][HID_];
    __shared__ __align__(16) float s_u[NNB][HID_];
    #pragma unroll
    for (int r = 0; r < NNB; r++) {
        s_h[r][tid]  = g_h[(i0+r)*HID_ + tid];
        s_am[r][tid] = g_aggm[(i0+r)*HID_ + tid];
    }
    __syncthreads();
    {
        ull acc[NNB];
        #pragma unroll
        for (int r = 0; r < NNB; r++) acc[r] = 0ULL;
        const float* wp = W1P + (tid << 2);
        #pragma unroll 1
        for (int k4 = 0; k4 < 32; k4++) {
            ulonglong2 w = ld2u(wp + k4*512);
            #pragma unroll
            for (int r = 0; r < NNB; r++) {
                ulonglong2 a = ld2u(&s_h[r][k4 << 2]);
                fma2(acc[r], a.x, w.x);
                fma2(acc[r], a.y, w.y);
            }
        }
        const float* wp2 = W1P + 32*512 + (tid << 2);
        #pragma unroll 1
        for (int k4 = 0; k4 < 32; k4++) {
            ulonglong2 w = ld2u(wp2 + k4*512);
            #pragma unroll
            for (int r = 0; r < NNB; r++) {
                ulonglong2 a = ld2u(&s_am[r][k4 << 2]);
                fma2(acc[r], a.x, w.x);
                fma2(acc[r], a.y, w.y);
            }
        }
        #pragma unroll
        for (int r = 0; r < NNB; r++) s_u[r][tid] = silu_f(hadd2(acc[r]));
    }
    __syncthreads();
    {
        ull acc[NNB];
        #pragma unroll
        for (int r = 0; r < NNB; r++) acc[r] = 0ULL;
        const float* wp = W2P + (tid << 2);
        #pragma unroll 1
        for (int k4 = 0; k4 < 32; k4++) {
            ulonglong2 w = ld2u(wp + k4*512);
            #pragma unroll
            for (int r = 0; r < NNB; r++) {
                ulonglong2 a = ld2u(&s_u[r][k4 << 2]);
                fma2(acc[r], a.x, w.x);
                fma2(acc[r], a.y, w.y);
            }
        }
        #pragma unroll
        for (int r = 0; r < NNB; r++)
            g_h[(i0+r)*HID_ + tid] = s_h[r][tid] + hadd2(acc[r]);
    }
}

// ---------------------------------------------------------------------------
// Final: logits = silu(silu(h) @ Wf1) @ Wf2 ; emit [logits | X] fp32
// ---------------------------------------------------------------------------
__global__ void __launch_bounds__(128) final_kernel(float* __restrict__ out) {
    int i0  = blockIdx.x * NNB;
    int tid = threadIdx.x;
    __shared__ __align__(16) float s1[NNB][HID_];
    __shared__ __align__(16) float s_u[NNB][HID_];
    #pragma unroll
    for (int r = 0; r < NNB; r++)
        s1[r][tid] = silu_f(g_h[(i0+r)*HID_ + tid]);
    __syncthreads();
    {
        ull acc[NNB];
        #pragma unroll
        for (int r = 0; r < NNB; r++) acc[r] = 0ULL;
        const float* wp = g_Wf1P + (tid << 2);
        #pragma unroll 1
        for (int k4 = 0; k4 < 32; k4++) {
            ulonglong2 w = ld2u(wp + k4*512);
            #pragma unroll
            for (int r = 0; r < NNB; r++) {
                ulonglong2 a = ld2u(&s1[r][k4 << 2]);
                fma2(acc[r], a.x, w.x);
                fma2(acc[r], a.y, w.y);
            }
        }
        #pragma unroll
        for (int r = 0; r < NNB; r++) s_u[r][tid] = silu_f(hadd2(acc[r]));
    }
    __syncthreads();
    for (int q = tid; q < NNB*NCLS_; q += 128) {
        int r = q / NCLS_, c = q - r*NCLS_;
        ull a2 = 0ULL;
        const float* wrow = &g_Wf2T[c][0];
        #pragma unroll 1
        for (int k4 = 0; k4 < 32; k4++) {
            ulonglong2 w = ld2u(wrow + (k4 << 2));
            ulonglong2 a = ld2u(&s_u[r][k4 << 2]);
            fma2(a2, a.x, w.x);
            fma2(a2, a.y, w.y);
        }
        out[(size_t)(i0+r)*NCLS_ + c] = hadd2(a2);
    }
    // final X lives in g_X[0] after 3 layers (0->buf0, 1->buf1, 2->buf0)
    const float* Xf = g_X[0];
    for (int idx = tid; idx < NNB*XDIM; idx += 128)
        out[(size_t)N_*NCLS_ + (size_t)i0*XDIM + idx] = Xf[(size_t)i0*XDIM + idx];
}

// ---------------------------------------------------------------------------
extern "C" void kernel_launch(void* const* d_in, const int* in_sizes, int n_in,
                              void* d_out, int out_size)
{
    const float* X     = (const float*)d_in[0];
    const int*   S     = (const int*)  d_in[1];
    const float* E_tab = (const float*)d_in[2];
    const float* Wchan = (const float*)d_in[3];
    const float* Win   = (const float*)d_in[4];
    const float* Wr    = (const float*)d_in[5];
    const float* We1   = (const float*)d_in[6];
    const float* be1   = (const float*)d_in[7];
    const float* We2   = (const float*)d_in[8];
    const float* Wx1   = (const float*)d_in[9];
    const float* Wx2   = (const float*)d_in[10];
    const float* Wh1   = (const float*)d_in[11];
    const float* Wh2   = (const float*)d_in[12];
    const float* Wf1   = (const float*)d_in[13];
    const float* Wf2   = (const float*)d_in[14];
    float* out = (float*)d_out;

    // Weight repacks (one-time per launch; tiny)
    for (int l = 0; l < 3; l++) {
        pack_kernel<<<(196*128 + 255)/256, 256>>>(Wr  + (size_t)l*196*128, 0, l, 196);
        pack_kernel<<<(384*128 + 255)/256, 256>>>(We1 + (size_t)l*384*128, 1, l, 384);
        pack_kernel<<<(128*128 + 255)/256, 256>>>(We2 + (size_t)l*128*128, 2, l, 128);
        pack_kernel<<<(128*128 + 255)/256, 256>>>(Wx1 + (size_t)l*128*128, 3, l, 128);
        pack_kernel<<<(256*128 + 255)/256, 256>>>(Wh1 + (size_t)l*256*128, 4, l, 256);
        pack_kernel<<<(128*128 + 255)/256, 256>>>(Wh2 + (size_t)l*128*128, 5, l, 128);
        tr_kernel<<<(128*C_ + 255)/256, 256>>>(Wx2 + (size_t)l*128*C_, 0, l, 128, C_);
    }
    pack_kernel<<<(128*128 + 255)/256, 256>>>(Wf1, 6, 0, 128);
    tr_kernel<<<(128*NCLS_ + 255)/256, 256>>>(Wf2, 1, 0, 128, NCLS_);

    dim3 kg((LPC + 255) / 256, NB);
    knn_kernel<<<kg, 256>>>(X);
    class_kernel<<<NCLS_, HID_>>>(E_tab, Win, Wchan);
    gather_h_kernel<<<(N_*HID_ + 255) / 256, 256>>>(S);

    for (int l = 0; l < 3; l++) {
        edge_kernel<<<N_/NPB, 128>>>(l, X, S, be1 + (size_t)l * HID_);
        node_kernel<<<N_/NNB, 128>>>(l);
    }

    final_kernel<<<N_/NNB, 128>>>(out);
}

// round 5
// speedup vs baseline: 1.0728x; 1.0011x over previous
#include <cuda_runtime.h>

// Problem constants
#define NB    8
#define LPC   2500
#define C_    14
#define K_    9
#define N_    (NB*LPC)     // 20000
#define E_    (N_*K_)      // 180000
#define HID_  128
#define NCLS_ 20
#define XDIM  (C_*3)       // 42

#define NPB   2            // nodes per edge-block
#define ROWS  (NPB*K_)     // 18 edges per block
#define NNB   16           // nodes per node/final block

typedef unsigned long long ull;

// Scratch (static device globals; no allocation allowed)
__device__ __align__(16) float g_X[2][N_*XDIM];
__device__ __align__(16) float g_h[N_*HID_];
__device__ __align__(16) float g_aggm[N_*HID_];
__device__ int   g_dst[E_];
__device__ __align__(16) float g_classh[NCLS_*HID_];
__device__ float g_classcw[NCLS_*C_];

// Packed weights: layout [k/4][128 cols][4 k] -> coalesced LDG.128, 4 k/thread
__device__ __align__(16) float g_WrP [3][49*128*4];   // k=196
__device__ __align__(16) float g_We1P[3][96*128*4];   // k=384
__device__ __align__(16) float g_We2P[3][32*128*4];   // k=128
__device__ __align__(16) float g_Wx1P[3][32*128*4];   // k=128
__device__ __align__(16) float g_Wh1P[3][64*128*4];   // k=256
__device__ __align__(16) float g_Wh2P[3][32*128*4];   // k=128
__device__ __align__(16) float g_Wf1P[32*128*4];      // k=128
// Small matrices: plain transpose [out_col][k]
__device__ __align__(16) float g_Wx2T[3][C_][HID_];
__device__ __align__(16) float g_Wf2T[NCLS_][HID_];

__device__ __forceinline__ float silu_f(float x) {
    return x * (1.0f / (1.0f + __expf(-x)));
}

// packed f32x2 FMA: acc.{lo,hi} += a.{lo,hi} * w.{lo,hi}
__device__ __forceinline__ void fma2(ull& acc, ull a, ull w) {
    asm("fma.rn.f32x2 %0, %1, %2, %0;" : "+l"(acc) : "l"(a), "l"(w));
}
__device__ __forceinline__ float hadd2(ull v) {
    unsigned lo, hi;
    asm("mov.b64 {%0,%1}, %2;" : "=r"(lo), "=r"(hi) : "l"(v));
    return __uint_as_float(lo) + __uint_as_float(hi);
}
__device__ __forceinline__ ulonglong2 ld2u(const float* p) {
    return *reinterpret_cast<const ulonglong2*>(p);
}

// ---------------------------------------------------------------------------
// Weight repack: in[k][128] -> out[k/4][128][4]
// ---------------------------------------------------------------------------
__global__ void __launch_bounds__(256) pack_kernel(
    const float* __restrict__ in, int which, int l, int Kk)
{
    int idx = blockIdx.x * 256 + threadIdx.x;
    if (idx >= Kk * 128) return;
    int k = idx >> 7, c = idx & 127;
    float v = in[k*128 + c];
    float* out;
    switch (which) {
        case 0: out = g_WrP[l];  break;
        case 1: out = g_We1P[l]; break;
        case 2: out = g_We2P[l]; break;
        case 3: out = g_Wx1P[l]; break;
        case 4: out = g_Wh1P[l]; break;
        case 5: out = g_Wh2P[l]; break;
        default: out = g_Wf1P;   break;
    }
    out[(k >> 2)*512 + (c << 2) + (k & 3)] = v;
}

// Plain transpose: in[R][Cc] -> out[Cc][R]
__global__ void __launch_bounds__(256) tr_kernel(
    const float* __restrict__ in, int which, int l, int R, int Cc)
{
    int idx = blockIdx.x * 256 + threadIdx.x;
    if (idx >= R * Cc) return;
    int r = idx / Cc, c = idx - r*Cc;
    float* out = (which == 0) ? &g_Wx2T[l][0][0] : &g_Wf2T[0][0];
    out[c*R + r] = in[r*Cc + c];
}

// ---------------------------------------------------------------------------
// kNN on CA coords (channel 1). One thread per query node, tiled candidates.
// ---------------------------------------------------------------------------
__global__ void __launch_bounds__(256) knn_kernel(const float* __restrict__ X) {
    int b = blockIdx.y;
    int q = blockIdx.x * 256 + threadIdx.x;
    __shared__ float sx[256], sy[256], sz[256];

    float qx = 0.f, qy = 0.f, qz = 0.f;
    if (q < LPC) {
        const float* p = X + ((size_t)(b*LPC + q) * C_ + 1) * 3;
        qx = p[0]; qy = p[1]; qz = p[2];
    }
    float best[K_]; int bidx[K_];
    #pragma unroll
    for (int k = 0; k < K_; k++) { best[k] = 3.0e38f; bidx[k] = 0; }

    for (int base = 0; base < LPC; base += 256) {
        int c = base + threadIdx.x;
        if (c < LPC) {
            const float* p = X + ((size_t)(b*LPC + c) * C_ + 1) * 3;
            sx[threadIdx.x] = p[0]; sy[threadIdx.x] = p[1]; sz[threadIdx.x] = p[2];
        }
        __syncthreads();
        int tl = min(256, LPC - base);
        if (q < LPC) {
            for (int j = 0; j < tl; j++) {
                int cj = base + j;
                if (cj == q) continue;
                float dx = qx - sx[j], dy = qy - sy[j], dz = qz - sz[j];
                float d2 = dx*dx + dy*dy + dz*dz;
                if (d2 < best[K_-1]) {
                    int pos = K_-1;
                    while (pos > 0 && best[pos-1] > d2) {
                        best[pos] = best[pos-1]; bidx[pos] = bidx[pos-1]; pos--;
                    }
                    best[pos] = d2; bidx[pos] = cj;
                }
            }
        }
        __syncthreads();
    }
    if (q < LPC) {
        int n = b*LPC + q;
        #pragma unroll
        for (int k = 0; k < K_; k++) g_dst[n*K_ + k] = b*LPC + bidx[k];
    }
}

// ---------------------------------------------------------------------------
// Per-class precompute: class_h = E_tab @ Win, class_cw = softmax(Wchan)
// ---------------------------------------------------------------------------
__global__ void __launch_bounds__(128) class_kernel(
    const float* __restrict__ E_tab, const float* __restrict__ Win,
    const float* __restrict__ Wchan)
{
    int c = blockIdx.x;
    int j = threadIdx.x;
    __shared__ float emb[HID_];
    emb[j] = E_tab[c*HID_ + j];
    __syncthreads();
    float acc = 0.f;
    #pragma unroll 4
    for (int k = 0; k < HID_; k++) acc += emb[k] * Win[k*HID_ + j];
    g_classh[c*HID_ + j] = acc;
    if (j == 0) {
        float w[C_]; float mx = -1e30f;
        #pragma unroll
        for (int a = 0; a < C_; a++) { w[a] = Wchan[c*C_ + a]; mx = fmaxf(mx, w[a]); }
        float s = 0.f;
        #pragma unroll
        for (int a = 0; a < C_; a++) { w[a] = expf(w[a] - mx); s += w[a]; }
        float inv = 1.0f / s;
        #pragma unroll
        for (int a = 0; a < C_; a++) g_classcw[c*C_ + a] = w[a] * inv;
    }
}

__global__ void __launch_bounds__(256) gather_h_kernel(const int* __restrict__ S) {
    int idx = blockIdx.x * 256 + threadIdx.x;
    if (idx < N_ * HID_) {
        int i = idx >> 7, j = idx & 127;
        g_h[idx] = g_classh[S[i]*HID_ + j];
    }
}

// ---------------------------------------------------------------------------
// Edge kernel: 2 source nodes (18 edges) per block. f32x2 inner loops,
// packed weights, shared-buffer aliasing.
// ---------------------------------------------------------------------------
__global__ void __launch_bounds__(128) edge_kernel(
    int layer, const float* __restrict__ Xext, const int* __restrict__ S,
    const float* __restrict__ be1)
{
    const float* Xin  = (layer == 0) ? Xext : g_X[(layer + 1) & 1];
    float*       Xout = g_X[layer & 1];
    const float* WrP  = g_WrP[layer];
    const float* We1P = g_We1P[layer];
    const float* We2P = g_We2P[layer];
    const float* Wx1P = g_Wx1P[layer];
    const float* Wx2T = &g_Wx2T[layer][0][0];

    const int tid = threadIdx.x;
    const int i0  = blockIdx.x * NPB;

    __shared__ __align__(16) float s_xd[ROWS][XDIM];
    __shared__ __align__(16) float s_hsrc[NPB][HID_];
    __shared__ __align__(16) float s_bufA[ROWS][HID_];   // hdst -> m
    __shared__ __align__(16) float s_bufB[ROWS][196];    // rad  -> m1 (first 128)
    __shared__ __align__(16) float s_bufC[ROWS][HID_];   // rf   -> t
    __shared__ float s_cw[ROWS][16];
    __shared__ int   s_dst[ROWS];

    if (tid < ROWS) s_dst[tid] = g_dst[i0*K_ + tid];
    #pragma unroll
    for (int p = 0; p < NPB; p++)
        s_hsrc[p][tid] = g_h[(i0+p)*HID_ + tid];
    __syncthreads();

    // h_dst gather (coalesced row loads)
    #pragma unroll
    for (int r = 0; r < ROWS; r++)
        s_bufA[r][tid] = g_h[(size_t)s_dst[r]*HID_ + tid];

    // xd = X[src] - X[dst]
    for (int idx = tid; idx < ROWS*XDIM; idx += 128) {
        int r = idx / XDIM, q = idx - r*XDIM;
        int p = r / K_;
        s_xd[r][q] = Xin[(size_t)(i0+p)*XDIM + q] - Xin[(size_t)s_dst[r]*XDIM + q];
    }
    __syncthreads();

    // rad[r][c*C+d] = dot3(xd[c], xd[d]) / C
    #pragma unroll 1
    for (int r = 0; r < ROWS; r++) {
        for (int p = tid; p < C_*C_; p += 128) {
            int c = p / C_, d = p - c*C_;
            const float* a = &s_xd[r][c*3];
            const float* b = &s_xd[r][d*3];
            s_bufB[r][p] = (a[0]*b[0] + a[1]*b[1] + a[2]*b[2]) * (1.0f/C_);
        }
    }
    __syncthreads();

    // rf = rad @ Wr -> bufC
    {
        ull acc[ROWS];
        #pragma unroll
        for (int r = 0; r < ROWS; r++) acc[r] = 0ULL;
        const float* wp = WrP + (tid << 2);
        #pragma unroll 1
        for (int k4 = 0; k4 < 49; k4++) {
            ulonglong2 w = ld2u(wp + k4*512);
            #pragma unroll
            for (int r = 0; r < ROWS; r++) {
                ulonglong2 a = ld2u(&s_bufB[r][k4 << 2]);
                fma2(acc[r], a.x, w.x);
                fma2(acc[r], a.y, w.y);
            }
        }
        #pragma unroll
        for (int r = 0; r < ROWS; r++) s_bufC[r][tid] = hadd2(acc[r]);
    }

    // per-node source base of We1 (first 128 k of We1)
    float base0, base1;
    {
        ull b[NPB];
        #pragma unroll
        for (int p = 0; p < NPB; p++) b[p] = 0ULL;
        const float* wp = We1P + (tid << 2);
        #pragma unroll 1
        for (int k4 = 0; k4 < 32; k4++) {
            ulonglong2 w = ld2u(wp + k4*512);
            #pragma unroll
            for (int p = 0; p < NPB; p++) {
                ulonglong2 a = ld2u(&s_hsrc[p][k4 << 2]);
                fma2(b[p], a.x, w.x);
                fma2(b[p], a.y, w.y);
            }
        }
        float bb = be1[tid];
        base0 = bb + hadd2(b[0]);
        base1 = bb + hadd2(b[1]);
    }
    __syncthreads();   // rf complete; rad fully consumed

    // m1 = silu(base + hdst@We1[128:256] + rf@We1[256:384]) -> bufB (stride 196)
    {
        ull acc[ROWS];
        #pragma unroll
        for (int r = 0; r < ROWS; r++) acc[r] = 0ULL;
        const float* wp = We1P + 32*512 + (tid << 2);
        #pragma unroll 1
        for (int k4 = 0; k4 < 32; k4++) {
            ulonglong2 w = ld2u(wp + k4*512);
            #pragma unroll
            for (int r = 0; r < ROWS; r++) {
                ulonglong2 a = ld2u(&s_bufA[r][k4 << 2]);
                fma2(acc[r], a.x, w.x);
                fma2(acc[r], a.y, w.y);
            }
        }
        const float* wp2 = We1P + 64*512 + (tid << 2);
        #pragma unroll 1
        for (int k4 = 0; k4 < 32; k4++) {
            ulonglong2 w = ld2u(wp2 + k4*512);
            #pragma unroll
            for (int r = 0; r < ROWS; r++) {
                ulonglong2 a = ld2u(&s_bufC[r][k4 << 2]);
                fma2(acc[r], a.x, w.x);
                fma2(acc[r], a.y, w.y);
            }
        }
        #pragma unroll
        for (int r = 0; r < ROWS; r++) {
            float v = ((r < K_) ? base0 : base1) + hadd2(acc[r]);
            s_bufB[r][tid] = silu_f(v);
        }
    }
    __syncthreads();

    // m = silu(m1 @ We2) -> bufA
    {
        ull acc[ROWS];
        #pragma unroll
        for (int r = 0; r < ROWS; r++) acc[r] = 0ULL;
        const float* wp = We2P + (tid << 2);
        #pragma unroll 1
        for (int k4 = 0; k4 < 32; k4++) {
            ulonglong2 w = ld2u(wp + k4*512);
            #pragma unroll
            for (int r = 0; r < ROWS; r++) {
                ulonglong2 a = ld2u(&s_bufB[r][k4 << 2]);
                fma2(acc[r], a.x, w.x);
                fma2(acc[r], a.y, w.y);
            }
        }
        #pragma unroll
        for (int r = 0; r < ROWS; r++) s_bufA[r][tid] = silu_f(hadd2(acc[r]));
    }
    __syncthreads();

    // t = silu(m @ Wx1) -> bufC
    {
        ull acc[ROWS];
        #pragma unroll
        for (int r = 0; r < ROWS; r++) acc[r] = 0ULL;
        const float* wp = Wx1P + (tid << 2);
        #pragma unroll 1
        for (int k4 = 0; k4 < 32; k4++) {
            ulonglong2 w = ld2u(wp + k4*512);
            #pragma unroll
            for (int r = 0; r < ROWS; r++) {
                ulonglong2 a = ld2u(&s_bufA[r][k4 << 2]);
                fma2(acc[r], a.x, w.x);
                fma2(acc[r], a.y, w.y);
            }
        }
        #pragma unroll
        for (int r = 0; r < ROWS; r++) s_bufC[r][tid] = silu_f(hadd2(acc[r]));
    }
    __syncthreads();

    // coef[r][c] = (t[r] . Wx2T[c]) * classcw ; 252 outputs
    for (int q = tid; q < ROWS*C_; q += 128) {
        int r = q / C_, c = q - r*C_;
        ull a2 = 0ULL;
        const float* wrow = Wx2T + c*HID_;
        #pragma unroll 1
        for (int k4 = 0; k4 < 32; k4++) {
            ulonglong2 w = ld2u(wrow + (k4 << 2));
            ulonglong2 a = ld2u(&s_bufC[r][k4 << 2]);
            fma2(a2, a.x, w.x);
            fma2(a2, a.y, w.y);
        }
        int p = r / K_;
        s_cw[r][c] = hadd2(a2) * g_classcw[S[i0+p]*C_ + c];
    }

    // aggm (reads bufA = m)
    #pragma unroll
    for (int p = 0; p < NPB; p++) {
        float am = 0.f;
        #pragma unroll
        for (int e = 0; e < K_; e++) am += s_bufA[p*K_ + e][tid];
        g_aggm[(i0+p)*HID_ + tid] = am;
    }
    __syncthreads();

    // X update (no atomics: all edges of node i live in this block)
    if (tid < NPB*XDIM) {
        int p = tid / XDIM, q = tid - p*XDIM, c = q / 3;
        float s = 0.f;
        #pragma unroll
        for (int e = 0; e < K_; e++) s += s_xd[p*K_ + e][q] * s_cw[p*K_ + e][c];
        Xout[(size_t)(i0+p)*XDIM + q] = Xin[(size_t)(i0+p)*XDIM + q] + s * (1.0f/K_);
    }
}

// ---------------------------------------------------------------------------
// Node update, 16 nodes per block: h += silu([h|aggm] @ Wh1) @ Wh2
// ---------------------------------------------------------------------------
__global__ void __launch_bounds__(128) node_kernel(int layer) {
    const float* W1P = g_Wh1P[layer];
    const float* W2P = g_Wh2P[layer];
    int i0  = blockIdx.x * NNB;
    int tid = threadIdx.x;
    __shared__ __align__(16) float s_h[NNB][HID_];
    __shared__ __align__(16) float s_am[NNB][HID_];
    __shared__ __align__(16) float s_u[NNB][HID_];
    #pragma unroll
    for (int r = 0; r < NNB; r++) {
        s_h[r][tid]  = g_h[(i0+r)*HID_ + tid];
        s_am[r][tid] = g_aggm[(i0+r)*HID_ + tid];
    }
    __syncthreads();
    {
        ull acc[NNB];
        #pragma unroll
        for (int r = 0; r < NNB; r++) acc[r] = 0ULL;
        const float* wp = W1P + (tid << 2);
        #pragma unroll 1
        for (int k4 = 0; k4 < 32; k4++) {
            ulonglong2 w = ld2u(wp + k4*512);
            #pragma unroll
            for (int r = 0; r < NNB; r++) {
                ulonglong2 a = ld2u(&s_h[r][k4 << 2]);
                fma2(acc[r], a.x, w.x);
                fma2(acc[r], a.y, w.y);
            }
        }
        const float* wp2 = W1P + 32*512 + (tid << 2);
        #pragma unroll 1
        for (int k4 = 0; k4 < 32; k4++) {
            ulonglong2 w = ld2u(wp2 + k4*512);
            #pragma unroll
            for (int r = 0; r < NNB; r++) {
                ulonglong2 a = ld2u(&s_am[r][k4 << 2]);
                fma2(acc[r], a.x, w.x);
                fma2(acc[r], a.y, w.y);
            }
        }
        #pragma unroll
        for (int r = 0; r < NNB; r++) s_u[r][tid] = silu_f(hadd2(acc[r]));
    }
    __syncthreads();
    {
        ull acc[NNB];
        #pragma unroll
        for (int r = 0; r < NNB; r++) acc[r] = 0ULL;
        const float* wp = W2P + (tid << 2);
        #pragma unroll 1
        for (int k4 = 0; k4 < 32; k4++) {
            ulonglong2 w = ld2u(wp + k4*512);
            #pragma unroll
            for (int r = 0; r < NNB; r++) {
                ulonglong2 a = ld2u(&s_u[r][k4 << 2]);
                fma2(acc[r], a.x, w.x);
                fma2(acc[r], a.y, w.y);
            }
        }
        #pragma unroll
        for (int r = 0; r < NNB; r++)
            g_h[(i0+r)*HID_ + tid] = s_h[r][tid] + hadd2(acc[r]);
    }
}

// ---------------------------------------------------------------------------
// Final: logits = silu(silu(h) @ Wf1) @ Wf2 ; emit [logits | X] fp32
// ---------------------------------------------------------------------------
__global__ void __launch_bounds__(128) final_kernel(float* __restrict__ out) {
    int i0  = blockIdx.x * NNB;
    int tid = threadIdx.x;
    __shared__ __align__(16) float s1[NNB][HID_];
    __shared__ __align__(16) float s_u[NNB][HID_];
    #pragma unroll
    for (int r = 0; r < NNB; r++)
        s1[r][tid] = silu_f(g_h[(i0+r)*HID_ + tid]);
    __syncthreads();
    {
        ull acc[NNB];
        #pragma unroll
        for (int r = 0; r < NNB; r++) acc[r] = 0ULL;
        const float* wp = g_Wf1P + (tid << 2);
        #pragma unroll 1
        for (int k4 = 0; k4 < 32; k4++) {
            ulonglong2 w = ld2u(wp + k4*512);
            #pragma unroll
            for (int r = 0; r < NNB; r++) {
                ulonglong2 a = ld2u(&s1[r][k4 << 2]);
                fma2(acc[r], a.x, w.x);
                fma2(acc[r], a.y, w.y);
            }
        }
        #pragma unroll
        for (int r = 0; r < NNB; r++) s_u[r][tid] = silu_f(hadd2(acc[r]));
    }
    __syncthreads();
    for (int q = tid; q < NNB*NCLS_; q += 128) {
        int r = q / NCLS_, c = q - r*NCLS_;
        ull a2 = 0ULL;
        const float* wrow = &g_Wf2T[c][0];
        #pragma unroll 1
        for (int k4 = 0; k4 < 32; k4++) {
            ulonglong2 w = ld2u(wrow + (k4 << 2));
            ulonglong2 a = ld2u(&s_u[r][k4 << 2]);
            fma2(a2, a.x, w.x);
            fma2(a2, a.y, w.y);
        }
        out[(size_t)(i0+r)*NCLS_ + c] = hadd2(a2);
    }
    // final X lives in g_X[0] after 3 layers (0->buf0, 1->buf1, 2->buf0)
    const float* Xf = g_X[0];
    for (int idx = tid; idx < NNB*XDIM; idx += 128)
        out[(size_t)N_*NCLS_ + (size_t)i0*XDIM + idx] = Xf[(size_t)i0*XDIM + idx];
}

// ---------------------------------------------------------------------------
extern "C" void kernel_launch(void* const* d_in, const int* in_sizes, int n_in,
                              void* d_out, int out_size)
{
    const float* X     = (const float*)d_in[0];
    const int*   S     = (const int*)  d_in[1];
    const float* E_tab = (const float*)d_in[2];
    const float* Wchan = (const float*)d_in[3];
    const float* Win   = (const float*)d_in[4];
    const float* Wr    = (const float*)d_in[5];
    const float* We1   = (const float*)d_in[6];
    const float* be1   = (const float*)d_in[7];
    const float* We2   = (const float*)d_in[8];
    const float* Wx1   = (const float*)d_in[9];
    const float* Wx2   = (const float*)d_in[10];
    const float* Wh1   = (const float*)d_in[11];
    const float* Wh2   = (const float*)d_in[12];
    const float* Wf1   = (const float*)d_in[13];
    const float* Wf2   = (const float*)d_in[14];
    float* out = (float*)d_out;

    // Weight repacks (one-time per launch; tiny)
    for (int l = 0; l < 3; l++) {
        pack_kernel<<<(196*128 + 255)/256, 256>>>(Wr  + (size_t)l*196*128, 0, l, 196);
        pack_kernel<<<(384*128 + 255)/256, 256>>>(We1 + (size_t)l*384*128, 1, l, 384);
        pack_kernel<<<(128*128 + 255)/256, 256>>>(We2 + (size_t)l*128*128, 2, l, 128);
        pack_kernel<<<(128*128 + 255)/256, 256>>>(Wx1 + (size_t)l*128*128, 3, l, 128);
        pack_kernel<<<(256*128 + 255)/256, 256>>>(Wh1 + (size_t)l*256*128, 4, l, 256);
        pack_kernel<<<(128*128 + 255)/256, 256>>>(Wh2 + (size_t)l*128*128, 5, l, 128);
        tr_kernel<<<(128*C_ + 255)/256, 256>>>(Wx2 + (size_t)l*128*C_, 0, l, 128, C_);
    }
    pack_kernel<<<(128*128 + 255)/256, 256>>>(Wf1, 6, 0, 128);
    tr_kernel<<<(128*NCLS_ + 255)/256, 256>>>(Wf2, 1, 0, 128, NCLS_);

    dim3 kg((LPC + 255) / 256, NB);
    knn_kernel<<<kg, 256>>>(X);
    class_kernel<<<NCLS_, HID_>>>(E_tab, Win, Wchan);
    gather_h_kernel<<<(N_*HID_ + 255) / 256, 256>>>(S);

    for (int l = 0; l < 3; l++) {
        edge_kernel<<<N_/NPB, 128>>>(l, X, S, be1 + (size_t)l * HID_);
        node_kernel<<<N_/NNB, 128>>>(l);
    }

    final_kernel<<<N_/NNB, 128>>>(out);
}